// round 1
// baseline (speedup 1.0000x reference)
#include <cuda_runtime.h>

// out[b][e] = sum_n v[b][n][e]
// Reference's softmax is over a size-1 axis => identically 1.0; everything
// except the v-reduction is dead code.

#define BSZ 32
#define NQ  2048
#define EMB 1024
#define NCHUNKS 32
#define NPER   (NQ / NCHUNKS)   // 64 rows per block

__global__ void zero_out_kernel(float* __restrict__ out, int n) {
    int i = blockIdx.x * blockDim.x + threadIdx.x;
    if (i < n) out[i] = 0.0f;
}

__global__ __launch_bounds__(256) void vsum_kernel(const float* __restrict__ v,
                                                   float* __restrict__ out) {
    const int b     = blockIdx.x;          // 0..31
    const int chunk = blockIdx.y;          // 0..31
    const int e4    = threadIdx.x;         // 0..255 -> float4 column index

    const float4* vp = reinterpret_cast<const float4*>(
                           v + (size_t)b * NQ * EMB + (size_t)chunk * NPER * EMB) + e4;

    float4 a0 = make_float4(0.f, 0.f, 0.f, 0.f);
    float4 a1 = make_float4(0.f, 0.f, 0.f, 0.f);

    // 64 rows, stride EMB/4 float4s (4 KB). Unroll for MLP; two accumulator
    // chains to break FADD dependency (lat 4).
    #pragma unroll 8
    for (int n = 0; n < NPER; n += 2) {
        float4 x0 = vp[(size_t)n * (EMB / 4)];
        float4 x1 = vp[(size_t)(n + 1) * (EMB / 4)];
        a0.x += x0.x; a0.y += x0.y; a0.z += x0.z; a0.w += x0.w;
        a1.x += x1.x; a1.y += x1.y; a1.z += x1.z; a1.w += x1.w;
    }

    float* o = out + (size_t)b * EMB + (size_t)e4 * 4;
    atomicAdd(o + 0, a0.x + a1.x);
    atomicAdd(o + 1, a0.y + a1.y);
    atomicAdd(o + 2, a0.z + a1.z);
    atomicAdd(o + 3, a0.w + a1.w);
}

extern "C" void kernel_launch(void* const* d_in, const int* in_sizes, int n_in,
                              void* d_out, int out_size) {
    // metadata order: q, k, v, Wq, bq, Wk, bk, Ws, bs
    const float* v = (const float*)d_in[2];
    float* out = (float*)d_out;

    // d_out is poisoned; zero it before accumulation.
    zero_out_kernel<<<(out_size + 255) / 256, 256>>>(out, out_size);

    dim3 grid(BSZ, NCHUNKS);
    vsum_kernel<<<grid, 256>>>(v, out);
}